// round 16
// baseline (speedup 1.0000x reference)
#include <cuda_runtime.h>
#include <cuda_fp16.h>
#include <cstdint>

// Problem constants
#define BB 128
#define TT 512
#define DD 512
#define HH 512
#define G4 2048            // 4*H
#define MX (BB*TT)

// Persistent-kernel tiling
#define NCTA 128
#define ROWS 32            // batch rows per CTA (one quarter)
#define NC   64            // permuted cols per CTA (=> 16 h cols)
#define AS2  260           // A-buffer stride in b32 units (256+4; %32==4 conflict-free)
#define BS2  260           // B-buffer stride in b32 units
#define ZST  68            // zs stride in floats

// SMEM word offsets (b32 units)
#define XB0_OFF 0
#define XB1_OFF (32 * AS2)                 // 8320
#define HB_OFF  (2 * 32 * AS2)             // 16640
#define WXS_OFF (3 * 32 * AS2)             // 24960
#define ZS_OFF  (WXS_OFF + 64 * BS2)       // 41600
#define SMEM_WORDS (ZS_OFF + 4 * 32 * ZST) // 50304 words = 201216 B

// Device scratch (allocation-free requirement: __device__ globals)
__device__ __half g_xh[(size_t)BB * TT * DD];  // 64 MB: X in fp16, [b][t][k]
__device__ __half g_WxT[G4 * DD];            // permuted input weights, TRANSPOSED [col'][k]
__device__ __half g_WhT[G4 * HH];            // permuted recurrent weights, TRANSPOSED [col'][k]
__device__ float  g_bp[G4];                  // permuted bias
__device__ __half g_hh[2][BB * HH];          // ping-pong hidden state (fp16, sorted order)
__device__ int    g_srcb[BB];                // sorted pos -> original batch row
__device__ int    g_nws[BB];                 // num_words, sorted descending
__device__ unsigned g_qcnt[4];               // per-quarter barrier counters

__device__ __forceinline__ uint32_t h2u(__half2 v) {
    return *reinterpret_cast<uint32_t*>(&v);
}

__device__ __forceinline__ void mma16h(float d[4], const uint32_t a[4], const uint32_t b[2]) {
    asm volatile(
        "mma.sync.aligned.m16n8k16.row.col.f32.f16.f16.f32 "
        "{%0,%1,%2,%3}, {%4,%5,%6,%7}, {%8,%9}, {%0,%1,%2,%3};"
        : "+f"(d[0]), "+f"(d[1]), "+f"(d[2]), "+f"(d[3])
        : "r"(a[0]), "r"(a[1]), "r"(a[2]), "r"(a[3]), "r"(b[0]), "r"(b[1]));
}

// ---------------------------------------------------------------------------
// Kernel 0: permute W (col' = 4*h + g) into fp16 transposed layouts, permute
// bias, AND (extra block 8192) sort batch rows by num_words descending.
// ---------------------------------------------------------------------------
__global__ void permute_W_kernel(const float* __restrict__ W, const float* __restrict__ bias,
                                 const int* __restrict__ nw) {
    if (blockIdx.x == 8192) {       // fused sort block
        int b = threadIdx.x;
        if (b < BB) {
            int my = nw[b];
            int rank = 0;
            for (int j = 0; j < BB; j++) {
                int v = nw[j];
                rank += (v > my) || (v == my && j < b);
            }
            g_srcb[rank] = b;
            g_nws[rank] = my;
        }
        return;
    }
    int idx = blockIdx.x * 256 + threadIdx.x;
    if (idx < 1024 * 2048) {
        int d = idx >> 11;
        int col = idx & 2047;
        int g = col >> 9;
        int h = col & 511;
        int colp = 4 * h + g;
        __half v = __float2half_rn(W[idx]);
        if (d < 512) g_WxT[(size_t)colp * 512 + d]         = v;
        else         g_WhT[(size_t)colp * 512 + (d - 512)] = v;
    }
    if (idx < 2048) {
        int g = idx >> 9;
        int h = idx & 511;
        g_bp[4 * h + g] = bias[idx];
    }
}

// ---------------------------------------------------------------------------
// Kernel 1: convert X fp32 -> fp16 (layout preserved [b][t][k]).
// ---------------------------------------------------------------------------
__global__ void convert_x_kernel(const float* __restrict__ X) {
    size_t i = ((size_t)blockIdx.x * 256 + threadIdx.x) * 8;
    float4 v0 = *(const float4*)(X + i);
    float4 v1 = *(const float4*)(X + i + 4);
    uint4 p;
    p.x = h2u(__floats2half2_rn(v0.x, v0.y));
    p.y = h2u(__floats2half2_rn(v0.z, v0.w));
    p.z = h2u(__floats2half2_rn(v1.x, v1.y));
    p.w = h2u(__floats2half2_rn(v1.z, v1.w));
    *(uint4*)(g_xh + i) = p;
}

// ---------------------------------------------------------------------------
// Kernel 2: init — reset counters, publish fp16 initial h (sorted order).
// ---------------------------------------------------------------------------
__global__ void init_state_kernel(const float* __restrict__ ih) {
    int i = blockIdx.x * 256 + threadIdx.x;
    if (i < 4) g_qcnt[i] = 0u;
    if (i < BB * HH) {
        int srow = i >> 9;
        int col = i & 511;
        int borig = g_srcb[srow];
        g_hh[0][i] = __float2half_rn(ih[borig * HH + col]);
    }
}

// ---------------------------------------------------------------------------
// Kernel 3: persistent FUSED LSTM, software-pipelined:
//   loop top: PER-WARP-PAIR h K-slice fill (own cp.async group + named
//   barrier, no CTA-wide wait) -> h-half GEMM (acc already holds x-half)
//   after epilogue: RELEASE, then out-store + x-half GEMM for t+1 inside the
//   barrier-wait window, then spin + sync.
// 128 CTAs = 4 sorted batch quarters x 32 col' chunks of 64.
// ---------------------------------------------------------------------------
__global__ void __launch_bounds__(256, 1) lstm_persist_kernel(
    const float* __restrict__ ic, const float* __restrict__ ih,
    float* __restrict__ out, float* __restrict__ c_final, float* __restrict__ h_final)
{
    extern __shared__ unsigned char smraw[];
    uint32_t* sw = (uint32_t*)smraw;
    uint32_t* xb[2] = { sw + XB0_OFF, sw + XB1_OFF };   // [32][AS2] fp16x2
    uint32_t* hb    = sw + HB_OFF;                       // [32][AS2] fp16x2
    uint32_t* wxs   = sw + WXS_OFF;                      // [64][BS2] WxT slice
    float*    zs    = (float*)(sw + ZS_OFF);             // [4][32][ZST]

    uint32_t sm_base;
    asm("{ .reg .u64 t; cvta.to.shared.u64 t, %1; cvt.u32.u64 %0, t; }"
        : "=r"(sm_base) : "l"(smraw));
    const uint32_t xb_base[2] = { sm_base + XB0_OFF * 4u, sm_base + XB1_OFF * 4u };
    const uint32_t hb_base = sm_base + HB_OFF * 4u;

    const int tid  = threadIdx.x;
    const int lane = tid & 31;
    const int warp = tid >> 5;
    const int rb = blockIdx.x & 3;        // batch quarter (sorted order)
    const int cn = blockIdx.x >> 2;       // 0..31 col' chunk
    const int n0 = cn * NC;               // col' base

    // --- one-time: stage WxT slice into SMEM ---
    {
        int cc  = tid >> 2;               // 0..63
        int seg = tid & 3;
        const uint4* src = (const uint4*)(g_WxT + (size_t)(n0 + cc) * 512 + seg * 128);
        uint32_t* dst = wxs + cc * BS2 + seg * 64;
        #pragma unroll
        for (int i = 0; i < 16; i++) {
            uint4 v = src[i];
            *(uint4*)(dst + i * 4) = v;
        }
    }

    // --- epilogue mapping: thread owns (srow, hc0) and (srow, hc0+1) ---
    const int r_ep = tid & 31;
    const int hl2  = (tid >> 5) * 2;
    const int srow = rb * ROWS + r_ep;
    const int borig = g_srcb[srow];
    const int mynw  = g_nws[srow];
    const int qmax  = g_nws[rb * ROWS];
    float c0  = ic[borig * HH + cn * 16 + hl2];
    float c1  = ic[borig * HH + cn * 16 + hl2 + 1];
    float hr0 = ih[borig * HH + cn * 16 + hl2];
    float hr1 = ih[borig * HH + cn * 16 + hl2 + 1];
    const size_t outcol = (size_t)borig * HH + cn * 16 + hl2;

    // preload bias for the 8 owned gate columns
    float bias8[8];
    #pragma unroll
    for (int i = 0; i < 8; i++) bias8[i] = g_bp[n0 + hl2 * 4 + i];

    // --- MMA mapping: 8 warps = 2 n-halves x 4 K-slices; warp tile 32x32 ---
    const int wn = warp & 1;
    const int kw = warp >> 1;
    const int kwb = kw * 64;                   // K-slice base in b32 units
    const int ln4 = lane >> 2;
    const int kl  = lane & 3;

    // --- x-fill mapping: full-CTA, 32 rows x 64 uint4; 8 uint4 per thread ---
    const int fr = tid >> 3;                   // row 0..31
    const int fc = tid & 7;                    // uint4 group
    const int borig_f = g_srcb[rb * ROWS + fr];

    // --- h-fill mapping: per warp-pair kw; 64 threads fill slice kw (8 KB) ---
    const int ptid  = tid & 63;
    const int prow  = ptid >> 1;               // 0..31
    const int phalf = ptid & 1;                // half of the 256B row-slice

    unsigned* const qcnt = &g_qcnt[rb];

    // --- load Wh fragments into registers ONCE (direct from global) ---
    uint32_t breg[8][4][2];
    #pragma unroll
    for (int ks = 0; ks < 8; ks++) {
        const int kb = kwb + ks * 8 + kl;
        #pragma unroll
        for (int u = 0; u < 4; u++) {
            int cc = wn * 32 + u * 8 + ln4;
            const uint32_t* wrow = (const uint32_t*)(g_WhT + (size_t)(n0 + cc) * 512);
            breg[ks][u][0] = wrow[kb];
            breg[ks][u][1] = wrow[kb + 4];
        }
    }
    __syncthreads();                           // wxs staged

    float acc[2][4][4];

    // --- prologue: fill x0, compute its x-half into acc, prefetch x1 ---
    if (qmax > 0) {
        const __half* src = g_xh + ((size_t)borig_f * TT) * 512 + fc * 8;
        uint32_t dstb = xb_base[0] + (uint32_t)(fr * AS2 + fc * 4) * 4u;
        #pragma unroll
        for (int j = 0; j < 8; j++) {
            asm volatile("cp.async.cg.shared.global [%0], [%1], 16;"
                         :: "r"(dstb + (uint32_t)(j * 32 * 4)),
                            "l"(src + j * 64) : "memory");
        }
        asm volatile("cp.async.commit_group;" ::: "memory");
        asm volatile("cp.async.wait_group 0;" ::: "memory");
        __syncthreads();

        #pragma unroll
        for (int s = 0; s < 2; s++)
            #pragma unroll
            for (int u = 0; u < 4; u++)
                #pragma unroll
                for (int i = 0; i < 4; i++) acc[s][u][i] = 0.f;

        uint32_t* x0 = xb[0];
        #pragma unroll
        for (int ks = 0; ks < 8; ks++) {
            const int kb = kwb + ks * 8 + kl;
            uint32_t a[2][4], bb[4][2];
            #pragma unroll
            for (int s = 0; s < 2; s++) {
                int rr = s * 16 + ln4;
                a[s][0] = x0[rr * AS2 + kb];
                a[s][1] = x0[(rr + 8) * AS2 + kb];
                a[s][2] = x0[rr * AS2 + kb + 4];
                a[s][3] = x0[(rr + 8) * AS2 + kb + 4];
            }
            #pragma unroll
            for (int u = 0; u < 4; u++) {
                int cc = wn * 32 + u * 8 + ln4;
                bb[u][0] = wxs[cc * BS2 + kb];
                bb[u][1] = wxs[cc * BS2 + kb + 4];
            }
            #pragma unroll
            for (int s = 0; s < 2; s++)
                #pragma unroll
                for (int u = 0; u < 4; u++)
                    mma16h(acc[s][u], a[s], bb[u]);
        }

        if (qmax > 1) {     // prefetch x1
            const __half* s1 = g_xh + ((size_t)borig_f * TT + 1) * 512 + fc * 8;
            uint32_t d1 = xb_base[1] + (uint32_t)(fr * AS2 + fc * 4) * 4u;
            #pragma unroll
            for (int j = 0; j < 8; j++) {
                asm volatile("cp.async.cg.shared.global [%0], [%1], 16;"
                             :: "r"(d1 + (uint32_t)(j * 32 * 4)),
                                "l"(s1 + j * 64) : "memory");
            }
            asm volatile("cp.async.commit_group;" ::: "memory");
        }
    }

    for (int t = 0; t < qmax; t++) {
        const __half* __restrict__ h_in  = g_hh[t & 1];
        __half*       __restrict__ h_out = g_hh[(t & 1) ^ 1];

        // per-warp-pair h K-slice fill: pair kw loads its own 8 KB slice,
        // waits on its OWN async group, then joins partner via named barrier.
        {
            const __half* src = h_in + (size_t)(rb * ROWS + prow) * HH
                              + kw * 128 + phalf * 64;
            uint32_t dstb = hb_base + (uint32_t)(prow * AS2 + kwb + phalf * 32) * 4u;
            #pragma unroll
            for (int j = 0; j < 8; j++) {
                asm volatile("cp.async.cg.shared.global [%0], [%1], 16;"
                             :: "r"(dstb + (uint32_t)(j * 16)),
                                "l"(src + j * 8) : "memory");
            }
            asm volatile("cp.async.commit_group;" ::: "memory");
            asm volatile("cp.async.wait_group 0;" ::: "memory");  // own slice (+x pending)
            asm volatile("bar.sync %0, 64;" :: "r"(kw + 1) : "memory");
        }

        // h-half GEMM (B in registers); acc already holds the x contribution
        #pragma unroll
        for (int ks = 0; ks < 8; ks++) {
            const int kb = kwb + ks * 8 + kl;
            uint32_t a[2][4];
            #pragma unroll
            for (int s = 0; s < 2; s++) {
                int rr = s * 16 + ln4;
                a[s][0] = hb[rr * AS2 + kb];
                a[s][1] = hb[(rr + 8) * AS2 + kb];
                a[s][2] = hb[rr * AS2 + kb + 4];
                a[s][3] = hb[(rr + 8) * AS2 + kb + 4];
            }
            #pragma unroll
            for (int s = 0; s < 2; s++)
                #pragma unroll
                for (int u = 0; u < 4; u++)
                    mma16h(acc[s][u], a[s], breg[ks][u]);
        }

        // store partials: zs[kw][row][col]
        {
            int zcb = wn * 32 + 2 * kl;
            #pragma unroll
            for (int s = 0; s < 2; s++) {
                int row = s * 16 + ln4;
                #pragma unroll
                for (int u = 0; u < 4; u++) {
                    int col = zcb + u * 8;
                    *(float2*)&zs[(kw * 32 + row) * ZST + col]     =
                        make_float2(acc[s][u][0], acc[s][u][1]);
                    *(float2*)&zs[(kw * 32 + row + 8) * ZST + col] =
                        make_float2(acc[s][u][2], acc[s][u][3]);
                }
            }
        }
        __syncthreads();

        // reduce 4 K-partials + bias + fused gate epilogue (2 owned h cols)
        float4 z0 = make_float4(bias8[0], bias8[1], bias8[2], bias8[3]);
        float4 z1 = make_float4(bias8[4], bias8[5], bias8[6], bias8[7]);
        #pragma unroll
        for (int s = 0; s < 4; s++) {
            const float* zp = zs + ((s * 32 + r_ep) * ZST + hl2 * 4);
            float4 a0 = *(const float4*)zp;
            float4 a1 = *(const float4*)(zp + 4);
            z0.x += a0.x; z0.y += a0.y; z0.z += a0.z; z0.w += a0.w;
            z1.x += a1.x; z1.y += a1.y; z1.z += a1.z; z1.w += a1.w;
        }

        float si0 = 1.f / (1.f + __expf(-z0.x));
        float sf0 = 1.f / (1.f + __expf(-(z0.z + 1.0f)));
        float so0 = 1.f / (1.f + __expf(-z0.w));
        float tj0 = tanhf(z0.y);
        float nc0 = c0 * sf0 + si0 * tj0;
        float nh0 = tanhf(nc0) * so0;

        float si1 = 1.f / (1.f + __expf(-z1.x));
        float sf1 = 1.f / (1.f + __expf(-(z1.z + 1.0f)));
        float so1 = 1.f / (1.f + __expf(-z1.w));
        float tj1 = tanhf(z1.y);
        float nc1 = c1 * sf1 + si1 * tj1;
        float nh1 = tanhf(nc1) * so1;

        bool m = t < mynw;
        c0 = m ? nc0 : c0;   c1 = m ? nc1 : c1;
        hr0 = m ? nh0 : hr0; hr1 = m ? nh1 : hr1;

        size_t sidx = (size_t)srow * HH + cn * 16 + hl2;
        *(__half2*)(h_out + sidx) = __floats2half2_rn(hr0, hr1);

        // barrier + overlapped out-store and x-half for step t+1
        if (t + 1 < qmax) {
            __syncthreads();                       // all h_out stores issued CTA-wide
            if (tid == 0) {
                asm volatile("red.release.gpu.add.u32 [%0], %1;"
                             :: "l"(qcnt), "r"(1u) : "memory");
            }

            // out store — off the inter-CTA critical path
            __stcs((float2*)&out[(size_t)t * (BB * HH) + outcol],
                   make_float2(m ? nh0 : 0.f, m ? nh1 : 0.f));

            // prefetch x(t+2) into the buffer x(t) just vacated
            if (t + 2 < qmax) {
                const __half* s2 = g_xh + ((size_t)borig_f * TT + (t + 2)) * 512 + fc * 8;
                uint32_t d2 = xb_base[t & 1] + (uint32_t)(fr * AS2 + fc * 4) * 4u;
                #pragma unroll
                for (int j = 0; j < 8; j++) {
                    asm volatile("cp.async.cg.shared.global [%0], [%1], 16;"
                                 :: "r"(d2 + (uint32_t)(j * 32 * 4)),
                                    "l"(s2 + j * 64) : "memory");
                }
                asm volatile("cp.async.commit_group;" ::: "memory");
            }

            // x-half GEMM for step t+1 — inside the barrier-wait window
            #pragma unroll
            for (int s = 0; s < 2; s++)
                #pragma unroll
                for (int u = 0; u < 4; u++)
                    #pragma unroll
                    for (int i = 0; i < 4; i++) acc[s][u][i] = 0.f;

            uint32_t* xn = xb[(t + 1) & 1];
            #pragma unroll
            for (int ks = 0; ks < 8; ks++) {
                const int kb = kwb + ks * 8 + kl;
                uint32_t a[2][4], bb[4][2];
                #pragma unroll
                for (int s = 0; s < 2; s++) {
                    int rr = s * 16 + ln4;
                    a[s][0] = xn[rr * AS2 + kb];
                    a[s][1] = xn[(rr + 8) * AS2 + kb];
                    a[s][2] = xn[rr * AS2 + kb + 4];
                    a[s][3] = xn[(rr + 8) * AS2 + kb + 4];
                }
                #pragma unroll
                for (int u = 0; u < 4; u++) {
                    int cc = wn * 32 + u * 8 + ln4;
                    bb[u][0] = wxs[cc * BS2 + kb];
                    bb[u][1] = wxs[cc * BS2 + kb + 4];
                }
                #pragma unroll
                for (int s = 0; s < 2; s++)
                    #pragma unroll
                    for (int u = 0; u < 4; u++)
                        mma16h(acc[s][u], a[s], bb[u]);
            }

            if (tid == 0) {
                unsigned target = 32u * (unsigned)(t + 1);
                unsigned v;
                do {
                    asm volatile("ld.acquire.gpu.u32 %0, [%1];"
                                 : "=r"(v) : "l"(qcnt) : "memory");
                } while (v < target);
            }
            __syncthreads();                       // acquire propagates CTA-wide
        } else {
            __stcs((float2*)&out[(size_t)t * (BB * HH) + outcol],
                   make_float2(m ? nh0 : 0.f, m ? nh1 : 0.f));
        }
    }

    // bulk zeros for the inactive tail (off the critical path)
    for (int t = qmax; t < TT; t++)
        __stcs((float2*)&out[(size_t)t * (BB * HH) + outcol], make_float2(0.f, 0.f));

    // final states (each (b,h) pair owned by exactly one thread)
    *(float2*)&c_final[outcol] = make_float2(c0, c1);
    *(float2*)&h_final[outcol] = make_float2(hr0, hr1);
}

// ---------------------------------------------------------------------------
extern "C" void kernel_launch(void* const* d_in, const int* in_sizes, int n_in,
                              void* d_out, int out_size) {
    const float* x    = (const float*)d_in[0];  // [B,T,D]
    const int*   nw   = (const int*)  d_in[1];  // [B]
    const float* ic   = (const float*)d_in[2];  // [B,H]
    const float* ih   = (const float*)d_in[3];  // [B,H]
    const float* W    = (const float*)d_in[4];  // [D+H, 4H]
    const float* bias = (const float*)d_in[5];  // [4H]

    float* out     = (float*)d_out;
    float* c_final = out + (size_t)TT * BB * HH;
    float* h_final = c_final + (size_t)BB * HH;

    const int smem_bytes = SMEM_WORDS * 4;              // 201216
    cudaFuncSetAttribute(lstm_persist_kernel,
                         cudaFuncAttributeMaxDynamicSharedMemorySize, smem_bytes);

    permute_W_kernel<<<8193, 256>>>(W, bias, nw);       // includes fused sort block
    convert_x_kernel<<<(BB * TT * DD) / (256 * 8), 256>>>(x);
    init_state_kernel<<<(BB * HH + 255) / 256, 256>>>(ih);
    lstm_persist_kernel<<<NCTA, 256, smem_bytes>>>(ic, ih, out, c_final, h_final);
}

// round 17
// speedup vs baseline: 1.2256x; 1.2256x over previous
#include <cuda_runtime.h>
#include <cuda_fp16.h>
#include <cstdint>

// Problem constants
#define BB 128
#define TT 512
#define DD 512
#define HH 512
#define G4 2048            // 4*H
#define MX (BB*TT)

// Persistent-kernel tiling
#define NCTA 128
#define ROWS 32            // batch rows per CTA (one quarter)
#define NC   64            // permuted cols per CTA (=> 16 h cols)
#define AS2  260           // A-buffer stride in b32 units (256+4; %32==4 conflict-free)
#define BS2  260           // B-buffer stride in b32 units
#define ZST  68            // zs stride in floats

// SMEM word offsets (b32 units)
#define XB0_OFF 0
#define XB1_OFF (32 * AS2)                 // 8320
#define HB_OFF  (2 * 32 * AS2)             // 16640
#define WXS_OFF (3 * 32 * AS2)             // 24960
#define ZS_OFF  (WXS_OFF + 64 * BS2)       // 41600
#define SMEM_WORDS (ZS_OFF + 4 * 32 * ZST) // 50304 words = 201216 B

// Device scratch (allocation-free requirement: __device__ globals)
__device__ __half g_xh[(size_t)BB * TT * DD];  // 64 MB: X in fp16, [b][t][k]
__device__ __half g_WxT[G4 * DD];            // permuted input weights, TRANSPOSED [col'][k]
__device__ __half g_WhT[G4 * HH];            // permuted recurrent weights, TRANSPOSED [col'][k]
__device__ float  g_bp[G4];                  // permuted bias
__device__ __half g_hh[2][BB * HH];          // ping-pong hidden state (fp16, sorted order)
__device__ int    g_srcb[BB];                // sorted pos -> original batch row
__device__ int    g_nws[BB];                 // num_words, sorted descending
__device__ unsigned g_qcnt[4];               // per-quarter barrier counters

__device__ __forceinline__ uint32_t h2u(__half2 v) {
    return *reinterpret_cast<uint32_t*>(&v);
}

__device__ __forceinline__ float tanh_fast(float x) {
    float y;
    asm("tanh.approx.f32 %0, %1;" : "=f"(y) : "f"(x));
    return y;
}
__device__ __forceinline__ float sigmoid_fast(float x) {
    return fmaf(0.5f, tanh_fast(0.5f * x), 0.5f);
}

__device__ __forceinline__ void mma16h(float d[4], const uint32_t a[4], const uint32_t b[2]) {
    asm volatile(
        "mma.sync.aligned.m16n8k16.row.col.f32.f16.f16.f32 "
        "{%0,%1,%2,%3}, {%4,%5,%6,%7}, {%8,%9}, {%0,%1,%2,%3};"
        : "+f"(d[0]), "+f"(d[1]), "+f"(d[2]), "+f"(d[3])
        : "r"(a[0]), "r"(a[1]), "r"(a[2]), "r"(a[3]), "r"(b[0]), "r"(b[1]));
}

// ---------------------------------------------------------------------------
// Kernel 0: permute W (col' = 4*h + g) into fp16 transposed layouts, permute
// bias, AND (extra block 8192) sort batch rows by num_words descending.
// ---------------------------------------------------------------------------
__global__ void permute_W_kernel(const float* __restrict__ W, const float* __restrict__ bias,
                                 const int* __restrict__ nw) {
    if (blockIdx.x == 8192) {       // fused sort block
        int b = threadIdx.x;
        if (b < BB) {
            int my = nw[b];
            int rank = 0;
            for (int j = 0; j < BB; j++) {
                int v = nw[j];
                rank += (v > my) || (v == my && j < b);
            }
            g_srcb[rank] = b;
            g_nws[rank] = my;
        }
        return;
    }
    int idx = blockIdx.x * 256 + threadIdx.x;
    if (idx < 1024 * 2048) {
        int d = idx >> 11;
        int col = idx & 2047;
        int g = col >> 9;
        int h = col & 511;
        int colp = 4 * h + g;
        __half v = __float2half_rn(W[idx]);
        if (d < 512) g_WxT[(size_t)colp * 512 + d]         = v;
        else         g_WhT[(size_t)colp * 512 + (d - 512)] = v;
    }
    if (idx < 2048) {
        int g = idx >> 9;
        int h = idx & 511;
        g_bp[4 * h + g] = bias[idx];
    }
}

// ---------------------------------------------------------------------------
// Kernel 1: convert X fp32 -> fp16 (layout preserved [b][t][k]).
// ---------------------------------------------------------------------------
__global__ void convert_x_kernel(const float* __restrict__ X) {
    size_t i = ((size_t)blockIdx.x * 256 + threadIdx.x) * 8;
    float4 v0 = *(const float4*)(X + i);
    float4 v1 = *(const float4*)(X + i + 4);
    uint4 p;
    p.x = h2u(__floats2half2_rn(v0.x, v0.y));
    p.y = h2u(__floats2half2_rn(v0.z, v0.w));
    p.z = h2u(__floats2half2_rn(v1.x, v1.y));
    p.w = h2u(__floats2half2_rn(v1.z, v1.w));
    *(uint4*)(g_xh + i) = p;
}

// ---------------------------------------------------------------------------
// Kernel 2: init — reset counters, publish fp16 initial h (sorted order).
// ---------------------------------------------------------------------------
__global__ void init_state_kernel(const float* __restrict__ ih) {
    int i = blockIdx.x * 256 + threadIdx.x;
    if (i < 4) g_qcnt[i] = 0u;
    if (i < BB * HH) {
        int srow = i >> 9;
        int col = i & 511;
        int borig = g_srcb[srow];
        g_hh[0][i] = __float2half_rn(ih[borig * HH + col]);
    }
}

// ---------------------------------------------------------------------------
// Kernel 3: persistent FUSED LSTM, software-pipelined (R15 structure):
//   loop top: CTA-wide h fill -> h-half GEMM (acc already holds x-half)
//   after epilogue: RELEASE, then out-store + x prefetch + x-half GEMM for
//   t+1 inside the barrier-wait window, then spin + sync.
// Fast epilogue: tanh.approx.f32 (+ sigmoid via tanh) shortens the
// inter-CTA critical path (epilogue precedes h store/release).
// 128 CTAs = 4 sorted batch quarters x 32 col' chunks of 64.
// ---------------------------------------------------------------------------
__global__ void __launch_bounds__(256, 1) lstm_persist_kernel(
    const float* __restrict__ ic, const float* __restrict__ ih,
    float* __restrict__ out, float* __restrict__ c_final, float* __restrict__ h_final)
{
    extern __shared__ unsigned char smraw[];
    uint32_t* sw = (uint32_t*)smraw;
    uint32_t* xb[2] = { sw + XB0_OFF, sw + XB1_OFF };   // [32][AS2] fp16x2
    uint32_t* hb    = sw + HB_OFF;                       // [32][AS2] fp16x2
    uint32_t* wxs   = sw + WXS_OFF;                      // [64][BS2] WxT slice
    float*    zs    = (float*)(sw + ZS_OFF);             // [4][32][ZST]

    uint32_t sm_base;
    asm("{ .reg .u64 t; cvta.to.shared.u64 t, %1; cvt.u32.u64 %0, t; }"
        : "=r"(sm_base) : "l"(smraw));
    const uint32_t xb_base[2] = { sm_base + XB0_OFF * 4u, sm_base + XB1_OFF * 4u };
    const uint32_t hb_base = sm_base + HB_OFF * 4u;

    const int tid  = threadIdx.x;
    const int lane = tid & 31;
    const int warp = tid >> 5;
    const int rb = blockIdx.x & 3;        // batch quarter (sorted order)
    const int cn = blockIdx.x >> 2;       // 0..31 col' chunk
    const int n0 = cn * NC;               // col' base

    // --- one-time: stage WxT slice into SMEM ---
    {
        int cc  = tid >> 2;               // 0..63
        int seg = tid & 3;
        const uint4* src = (const uint4*)(g_WxT + (size_t)(n0 + cc) * 512 + seg * 128);
        uint32_t* dst = wxs + cc * BS2 + seg * 64;
        #pragma unroll
        for (int i = 0; i < 16; i++) {
            uint4 v = src[i];
            *(uint4*)(dst + i * 4) = v;
        }
    }

    // --- epilogue mapping: thread owns (srow, hc0) and (srow, hc0+1) ---
    const int r_ep = tid & 31;
    const int hl2  = (tid >> 5) * 2;
    const int srow = rb * ROWS + r_ep;
    const int borig = g_srcb[srow];
    const int mynw  = g_nws[srow];
    const int qmax  = g_nws[rb * ROWS];
    float c0  = ic[borig * HH + cn * 16 + hl2];
    float c1  = ic[borig * HH + cn * 16 + hl2 + 1];
    float hr0 = ih[borig * HH + cn * 16 + hl2];
    float hr1 = ih[borig * HH + cn * 16 + hl2 + 1];
    const size_t outcol = (size_t)borig * HH + cn * 16 + hl2;

    // preload bias for the 8 owned gate columns
    float bias8[8];
    #pragma unroll
    for (int i = 0; i < 8; i++) bias8[i] = g_bp[n0 + hl2 * 4 + i];

    // --- MMA mapping: 8 warps = 2 n-halves x 4 K-slices; warp tile 32x32 ---
    const int wn = warp & 1;
    const int kw = warp >> 1;
    const int kwb = kw * 64;                   // K-slice base in b32 units
    const int ln4 = lane >> 2;
    const int kl  = lane & 3;

    // --- fill mapping: 32 rows x 64 uint4 per buffer; 8 uint4 per thread ---
    const int fr = tid >> 3;                   // row 0..31
    const int fc = tid & 7;                    // uint4 group
    const int borig_f = g_srcb[rb * ROWS + fr];

    unsigned* const qcnt = &g_qcnt[rb];

    // --- load Wh fragments into registers ONCE (direct from global) ---
    uint32_t breg[8][4][2];
    #pragma unroll
    for (int ks = 0; ks < 8; ks++) {
        const int kb = kwb + ks * 8 + kl;
        #pragma unroll
        for (int u = 0; u < 4; u++) {
            int cc = wn * 32 + u * 8 + ln4;
            const uint32_t* wrow = (const uint32_t*)(g_WhT + (size_t)(n0 + cc) * 512);
            breg[ks][u][0] = wrow[kb];
            breg[ks][u][1] = wrow[kb + 4];
        }
    }
    __syncthreads();                           // wxs staged

    float acc[2][4][4];

    // --- prologue: fill x0, compute its x-half into acc, prefetch x1 ---
    if (qmax > 0) {
        const __half* src = g_xh + ((size_t)borig_f * TT) * 512 + fc * 8;
        uint32_t dstb = xb_base[0] + (uint32_t)(fr * AS2 + fc * 4) * 4u;
        #pragma unroll
        for (int j = 0; j < 8; j++) {
            asm volatile("cp.async.cg.shared.global [%0], [%1], 16;"
                         :: "r"(dstb + (uint32_t)(j * 32 * 4)),
                            "l"(src + j * 64) : "memory");
        }
        asm volatile("cp.async.commit_group;" ::: "memory");
        asm volatile("cp.async.wait_group 0;" ::: "memory");
        __syncthreads();

        #pragma unroll
        for (int s = 0; s < 2; s++)
            #pragma unroll
            for (int u = 0; u < 4; u++)
                #pragma unroll
                for (int i = 0; i < 4; i++) acc[s][u][i] = 0.f;

        uint32_t* x0 = xb[0];
        #pragma unroll
        for (int ks = 0; ks < 8; ks++) {
            const int kb = kwb + ks * 8 + kl;
            uint32_t a[2][4], bb[4][2];
            #pragma unroll
            for (int s = 0; s < 2; s++) {
                int rr = s * 16 + ln4;
                a[s][0] = x0[rr * AS2 + kb];
                a[s][1] = x0[(rr + 8) * AS2 + kb];
                a[s][2] = x0[rr * AS2 + kb + 4];
                a[s][3] = x0[(rr + 8) * AS2 + kb + 4];
            }
            #pragma unroll
            for (int u = 0; u < 4; u++) {
                int cc = wn * 32 + u * 8 + ln4;
                bb[u][0] = wxs[cc * BS2 + kb];
                bb[u][1] = wxs[cc * BS2 + kb + 4];
            }
            #pragma unroll
            for (int s = 0; s < 2; s++)
                #pragma unroll
                for (int u = 0; u < 4; u++)
                    mma16h(acc[s][u], a[s], bb[u]);
        }

        if (qmax > 1) {     // prefetch x1
            const __half* s1 = g_xh + ((size_t)borig_f * TT + 1) * 512 + fc * 8;
            uint32_t d1 = xb_base[1] + (uint32_t)(fr * AS2 + fc * 4) * 4u;
            #pragma unroll
            for (int j = 0; j < 8; j++) {
                asm volatile("cp.async.cg.shared.global [%0], [%1], 16;"
                             :: "r"(d1 + (uint32_t)(j * 32 * 4)),
                                "l"(s1 + j * 64) : "memory");
            }
            asm volatile("cp.async.commit_group;" ::: "memory");
        }
    }

    for (int t = 0; t < qmax; t++) {
        const __half* __restrict__ h_in  = g_hh[t & 1];
        __half*       __restrict__ h_out = g_hh[(t & 1) ^ 1];

        // fill hbuf with this quarter's 32 h rows (valid after prev barrier)
        {
            const __half* src = h_in + (size_t)(rb * ROWS + fr) * HH + fc * 8;
            uint32_t dstb = hb_base + (uint32_t)(fr * AS2 + fc * 4) * 4u;
            #pragma unroll
            for (int j = 0; j < 8; j++) {
                asm volatile("cp.async.cg.shared.global [%0], [%1], 16;"
                             :: "r"(dstb + (uint32_t)(j * 32 * 4)),
                                "l"(src + j * 64) : "memory");
            }
            asm volatile("cp.async.commit_group;" ::: "memory");
            asm volatile("cp.async.wait_group 0;" ::: "memory");  // h (+ pending x) done
        }
        __syncthreads();

        // h-half GEMM (B in registers); acc already holds the x contribution
        #pragma unroll
        for (int ks = 0; ks < 8; ks++) {
            const int kb = kwb + ks * 8 + kl;
            uint32_t a[2][4];
            #pragma unroll
            for (int s = 0; s < 2; s++) {
                int rr = s * 16 + ln4;
                a[s][0] = hb[rr * AS2 + kb];
                a[s][1] = hb[(rr + 8) * AS2 + kb];
                a[s][2] = hb[rr * AS2 + kb + 4];
                a[s][3] = hb[(rr + 8) * AS2 + kb + 4];
            }
            #pragma unroll
            for (int s = 0; s < 2; s++)
                #pragma unroll
                for (int u = 0; u < 4; u++)
                    mma16h(acc[s][u], a[s], breg[ks][u]);
        }

        // store partials: zs[kw][row][col]
        {
            int zcb = wn * 32 + 2 * kl;
            #pragma unroll
            for (int s = 0; s < 2; s++) {
                int row = s * 16 + ln4;
                #pragma unroll
                for (int u = 0; u < 4; u++) {
                    int col = zcb + u * 8;
                    *(float2*)&zs[(kw * 32 + row) * ZST + col]     =
                        make_float2(acc[s][u][0], acc[s][u][1]);
                    *(float2*)&zs[(kw * 32 + row + 8) * ZST + col] =
                        make_float2(acc[s][u][2], acc[s][u][3]);
                }
            }
        }
        __syncthreads();

        // reduce 4 K-partials + bias + fast fused gate epilogue (2 h cols)
        float4 z0 = make_float4(bias8[0], bias8[1], bias8[2], bias8[3]);
        float4 z1 = make_float4(bias8[4], bias8[5], bias8[6], bias8[7]);
        #pragma unroll
        for (int s = 0; s < 4; s++) {
            const float* zp = zs + ((s * 32 + r_ep) * ZST + hl2 * 4);
            float4 a0 = *(const float4*)zp;
            float4 a1 = *(const float4*)(zp + 4);
            z0.x += a0.x; z0.y += a0.y; z0.z += a0.z; z0.w += a0.w;
            z1.x += a1.x; z1.y += a1.y; z1.z += a1.z; z1.w += a1.w;
        }

        float si0 = sigmoid_fast(z0.x);
        float sf0 = sigmoid_fast(z0.z + 1.0f);
        float so0 = sigmoid_fast(z0.w);
        float tj0 = tanh_fast(z0.y);
        float nc0 = c0 * sf0 + si0 * tj0;
        float nh0 = tanh_fast(nc0) * so0;

        float si1 = sigmoid_fast(z1.x);
        float sf1 = sigmoid_fast(z1.z + 1.0f);
        float so1 = sigmoid_fast(z1.w);
        float tj1 = tanh_fast(z1.y);
        float nc1 = c1 * sf1 + si1 * tj1;
        float nh1 = tanh_fast(nc1) * so1;

        bool m = t < mynw;
        c0 = m ? nc0 : c0;   c1 = m ? nc1 : c1;
        hr0 = m ? nh0 : hr0; hr1 = m ? nh1 : hr1;

        size_t sidx = (size_t)srow * HH + cn * 16 + hl2;
        *(__half2*)(h_out + sidx) = __floats2half2_rn(hr0, hr1);

        // barrier + overlapped out-store / x prefetch / x-half for step t+1
        if (t + 1 < qmax) {
            __syncthreads();                       // all h_out stores issued CTA-wide
            if (tid == 0) {
                asm volatile("red.release.gpu.add.u32 [%0], %1;"
                             :: "l"(qcnt), "r"(1u) : "memory");
            }

            // out store — off the inter-CTA critical path
            __stcs((float2*)&out[(size_t)t * (BB * HH) + outcol],
                   make_float2(m ? nh0 : 0.f, m ? nh1 : 0.f));

            // prefetch x(t+2) into the buffer x(t) just vacated
            if (t + 2 < qmax) {
                const __half* s2 = g_xh + ((size_t)borig_f * TT + (t + 2)) * 512 + fc * 8;
                uint32_t d2 = xb_base[t & 1] + (uint32_t)(fr * AS2 + fc * 4) * 4u;
                #pragma unroll
                for (int j = 0; j < 8; j++) {
                    asm volatile("cp.async.cg.shared.global [%0], [%1], 16;"
                                 :: "r"(d2 + (uint32_t)(j * 32 * 4)),
                                    "l"(s2 + j * 64) : "memory");
                }
                asm volatile("cp.async.commit_group;" ::: "memory");
            }

            // x-half GEMM for step t+1 — inside the barrier-wait window
            #pragma unroll
            for (int s = 0; s < 2; s++)
                #pragma unroll
                for (int u = 0; u < 4; u++)
                    #pragma unroll
                    for (int i = 0; i < 4; i++) acc[s][u][i] = 0.f;

            uint32_t* xn = xb[(t + 1) & 1];
            #pragma unroll
            for (int ks = 0; ks < 8; ks++) {
                const int kb = kwb + ks * 8 + kl;
                uint32_t a[2][4], bb[4][2];
                #pragma unroll
                for (int s = 0; s < 2; s++) {
                    int rr = s * 16 + ln4;
                    a[s][0] = xn[rr * AS2 + kb];
                    a[s][1] = xn[(rr + 8) * AS2 + kb];
                    a[s][2] = xn[rr * AS2 + kb + 4];
                    a[s][3] = xn[(rr + 8) * AS2 + kb + 4];
                }
                #pragma unroll
                for (int u = 0; u < 4; u++) {
                    int cc = wn * 32 + u * 8 + ln4;
                    bb[u][0] = wxs[cc * BS2 + kb];
                    bb[u][1] = wxs[cc * BS2 + kb + 4];
                }
                #pragma unroll
                for (int s = 0; s < 2; s++)
                    #pragma unroll
                    for (int u = 0; u < 4; u++)
                        mma16h(acc[s][u], a[s], bb[u]);
            }

            if (tid == 0) {
                unsigned target = 32u * (unsigned)(t + 1);
                unsigned v;
                do {
                    asm volatile("ld.acquire.gpu.u32 %0, [%1];"
                                 : "=r"(v) : "l"(qcnt) : "memory");
                } while (v < target);
            }
            __syncthreads();                       // acquire propagates CTA-wide
        } else {
            __stcs((float2*)&out[(size_t)t * (BB * HH) + outcol],
                   make_float2(m ? nh0 : 0.f, m ? nh1 : 0.f));
        }
    }

    // bulk zeros for the inactive tail (off the critical path)
    for (int t = qmax; t < TT; t++)
        __stcs((float2*)&out[(size_t)t * (BB * HH) + outcol], make_float2(0.f, 0.f));

    // final states (each (b,h) pair owned by exactly one thread)
    *(float2*)&c_final[outcol] = make_float2(c0, c1);
    *(float2*)&h_final[outcol] = make_float2(hr0, hr1);
}

// ---------------------------------------------------------------------------
extern "C" void kernel_launch(void* const* d_in, const int* in_sizes, int n_in,
                              void* d_out, int out_size) {
    const float* x    = (const float*)d_in[0];  // [B,T,D]
    const int*   nw   = (const int*)  d_in[1];  // [B]
    const float* ic   = (const float*)d_in[2];  // [B,H]
    const float* ih   = (const float*)d_in[3];  // [B,H]
    const float* W    = (const float*)d_in[4];  // [D+H, 4H]
    const float* bias = (const float*)d_in[5];  // [4H]

    float* out     = (float*)d_out;
    float* c_final = out + (size_t)TT * BB * HH;
    float* h_final = c_final + (size_t)BB * HH;

    const int smem_bytes = SMEM_WORDS * 4;              // 201216
    cudaFuncSetAttribute(lstm_persist_kernel,
                         cudaFuncAttributeMaxDynamicSharedMemorySize, smem_bytes);

    permute_W_kernel<<<8193, 256>>>(W, bias, nw);       // includes fused sort block
    convert_x_kernel<<<(BB * TT * DD) / (256 * 8), 256>>>(x);
    init_state_kernel<<<(BB * HH + 255) / 256, 256>>>(ih);
    lstm_persist_kernel<<<NCTA, 256, smem_bytes>>>(ic, ih, out, c_final, h_final);
}